// round 1
// baseline (speedup 1.0000x reference)
#include <cuda_runtime.h>
#include <cuda_bf16.h>
#include <cstdint>

// ============================================================================
// Problem: B=8, N=4096, D=256, QK=128, M=32
//   Q = H0 @ Wq          (B,N,QK)
//   K = X0 @ Wk          (B,N,QK)
//   sumexp[b,n] = sum_m exp( (Q[b,n,:]·K[b,m,:]) * QK^-0.5 )   (no max shift
//       needed: |S*scale| < ~1 for these inputs, fp32 exp-sum is safe)
//   w_keep = sumexp / sum(sumexp)          (== softmax(logsumexp(S)))
//   slot_w = softmax(slot_logits, axis=-1)
//   w = slot_w * w_keep; w /= (row_sum + 1e-6)
//   out = w @ H0
// ============================================================================

#define Bdim 8
#define Ndim 4096
#define Ddim 256
#define QKdim 128
#define Mdim 32

// -------- device scratch (no allocations allowed) --------
__device__ __nv_bfloat16 g_Qb[Bdim * Ndim * QKdim];     // 8 MB
__device__ __nv_bfloat16 g_Kb[Bdim * Ndim * QKdim];     // 8 MB
__device__ __nv_bfloat16 g_Wt[2][QKdim * Ddim];         // Wq^T, Wk^T (bf16)
__device__ float g_sumexp[Bdim * Ndim];
__device__ float g_wkeep[Bdim * Ndim];
__device__ float g_slotw[Mdim * Ndim];
__device__ float g_norm[Bdim * Mdim];
__device__ float g_part[Bdim * 32 * Mdim * Ddim];       // 8 MB partials

// ---------------------------------------------------------------------------
// bf16 MMA m16n8k16 (row.col, fp32 accum)
// ---------------------------------------------------------------------------
__device__ __forceinline__ void mma16816(float* c, const uint32_t* a, const uint32_t* b) {
    asm volatile(
        "mma.sync.aligned.m16n8k16.row.col.f32.bf16.bf16.f32 "
        "{%0,%1,%2,%3}, {%4,%5,%6,%7}, {%8,%9}, {%0,%1,%2,%3};"
        : "+f"(c[0]), "+f"(c[1]), "+f"(c[2]), "+f"(c[3])
        : "r"(a[0]), "r"(a[1]), "r"(a[2]), "r"(a[3]), "r"(b[0]), "r"(b[1]));
}

// ---------------------------------------------------------------------------
// K0: transpose + convert Wq, Wk to bf16  (Wt[z][q][d] = W[d][q])
// ---------------------------------------------------------------------------
__global__ void prep_wt_kernel(const float* __restrict__ Wq, const float* __restrict__ Wk) {
    int idx = blockIdx.x * blockDim.x + threadIdx.x;   // 32768 total
    if (idx < Ddim * QKdim) {
        int q = idx >> 8;        // 0..127
        int d = idx & 255;       // 0..255
        g_Wt[0][q * Ddim + d] = __float2bfloat16(Wq[d * QKdim + q]);
        g_Wt[1][q * Ddim + d] = __float2bfloat16(Wk[d * QKdim + q]);
    }
}

// ---------------------------------------------------------------------------
// K0b: slot_w = softmax(slot_logits, axis=-1).  32 blocks (one per slot).
// ---------------------------------------------------------------------------
__global__ void slot_softmax_kernel(const float* __restrict__ logits) {
    int m = blockIdx.x;
    int tid = threadIdx.x;
    __shared__ float sred[256];
    const float* row = logits + m * Ndim;

    float mx = -1e30f;
    for (int n = tid; n < Ndim; n += 256) mx = fmaxf(mx, row[n]);
    sred[tid] = mx; __syncthreads();
    for (int s = 128; s > 0; s >>= 1) { if (tid < s) sred[tid] = fmaxf(sred[tid], sred[tid + s]); __syncthreads(); }
    mx = sred[0]; __syncthreads();

    float sum = 0.f;
    for (int n = tid; n < Ndim; n += 256) sum += __expf(row[n] - mx);
    sred[tid] = sum; __syncthreads();
    for (int s = 128; s > 0; s >>= 1) { if (tid < s) sred[tid] += sred[tid + s]; __syncthreads(); }
    float inv = 1.0f / sred[0];

    for (int n = tid; n < Ndim; n += 256)
        g_slotw[m * Ndim + n] = __expf(row[n] - mx) * inv;
}

// ---------------------------------------------------------------------------
// K1: projection GEMM.  C[rows=128, 128] = A[rows,256](f32) @ Wt[z]^T (bf16)
//   grid (256 row-tiles, 2), 256 threads = 8 warps (2 along M x 4 along N)
//   warp tile 64x32, mma m16n8k16, fp32 accum -> bf16 out.
// ---------------------------------------------------------------------------
#define PLDA 40   // smem row stride (bf16 elems) for 32-wide k chunk, conflict-free

__global__ __launch_bounds__(256) void proj_kernel(const float* __restrict__ H0,
                                                   const float* __restrict__ X0) {
    const int z = blockIdx.y;
    const float* A = z ? X0 : H0;
    const __nv_bfloat16* W = g_Wt[z];
    __nv_bfloat16* Out = z ? g_Kb : g_Qb;
    const int row0 = blockIdx.x * 128;

    __shared__ __nv_bfloat16 As[128 * PLDA];
    __shared__ __nv_bfloat16 Bs[128 * PLDA];

    const int tid = threadIdx.x;
    const int wid = tid >> 5, lane = tid & 31;
    const int warp_m = wid >> 2, warp_n = wid & 3;
    const int q = lane >> 2, r = lane & 3;

    float c[4][4][4];
#pragma unroll
    for (int mi = 0; mi < 4; mi++)
#pragma unroll
        for (int ni = 0; ni < 4; ni++)
#pragma unroll
            for (int j = 0; j < 4; j++) c[mi][ni][j] = 0.f;

    for (int k0 = 0; k0 < Ddim; k0 += 32) {
        // stage A (f32 -> bf16): 128 rows x 32 k
        float4 av[4];
#pragma unroll
        for (int i = 0; i < 4; i++) {
            int lin = tid + i * 256;
            int row = lin >> 3, c4 = lin & 7;
            av[i] = *(const float4*)&A[(size_t)(row0 + row) * Ddim + k0 + c4 * 4];
        }
        // stage B (Wt bf16): 128 n x 32 k
        uint32_t bv[8];
#pragma unroll
        for (int i = 0; i < 8; i++) {
            int lin = tid + i * 256;
            int row = lin >> 4, cc = lin & 15;
            bv[i] = *(const uint32_t*)&W[row * Ddim + k0 + cc * 2];
        }
        __syncthreads();
#pragma unroll
        for (int i = 0; i < 4; i++) {
            int lin = tid + i * 256;
            int row = lin >> 3, c4 = lin & 7;
            __nv_bfloat162 p0, p1;
            p0.x = __float2bfloat16(av[i].x); p0.y = __float2bfloat16(av[i].y);
            p1.x = __float2bfloat16(av[i].z); p1.y = __float2bfloat16(av[i].w);
            *(__nv_bfloat162*)&As[row * PLDA + c4 * 4]     = p0;
            *(__nv_bfloat162*)&As[row * PLDA + c4 * 4 + 2] = p1;
        }
#pragma unroll
        for (int i = 0; i < 8; i++) {
            int lin = tid + i * 256;
            int row = lin >> 4, cc = lin & 15;
            *(uint32_t*)&Bs[row * PLDA + cc * 2] = bv[i];
        }
        __syncthreads();

#pragma unroll
        for (int ks = 0; ks < 32; ks += 16) {
            uint32_t af[4][4], bfg[4][2];
#pragma unroll
            for (int mi = 0; mi < 4; mi++) {
                const __nv_bfloat16* p = &As[(warp_m * 64 + mi * 16 + q) * PLDA + ks + 2 * r];
                af[mi][0] = *(const uint32_t*)p;
                af[mi][1] = *(const uint32_t*)(p + 8 * PLDA);
                af[mi][2] = *(const uint32_t*)(p + 8);
                af[mi][3] = *(const uint32_t*)(p + 8 * PLDA + 8);
            }
#pragma unroll
            for (int ni = 0; ni < 4; ni++) {
                const __nv_bfloat16* p = &Bs[(warp_n * 32 + ni * 8 + q) * PLDA + ks + 2 * r];
                bfg[ni][0] = *(const uint32_t*)p;
                bfg[ni][1] = *(const uint32_t*)(p + 8);
            }
#pragma unroll
            for (int mi = 0; mi < 4; mi++)
#pragma unroll
                for (int ni = 0; ni < 4; ni++)
                    mma16816(c[mi][ni], af[mi], bfg[ni]);
        }
        __syncthreads();
    }

    // epilogue -> bf16
#pragma unroll
    for (int mi = 0; mi < 4; mi++) {
        int row = row0 + warp_m * 64 + mi * 16 + q;
#pragma unroll
        for (int ni = 0; ni < 4; ni++) {
            int col = warp_n * 32 + ni * 8 + 2 * r;
            __nv_bfloat162 v0, v1;
            v0.x = __float2bfloat16(c[mi][ni][0]); v0.y = __float2bfloat16(c[mi][ni][1]);
            v1.x = __float2bfloat16(c[mi][ni][2]); v1.y = __float2bfloat16(c[mi][ni][3]);
            *(__nv_bfloat162*)&Out[(size_t)row * QKdim + col]        = v0;
            *(__nv_bfloat162*)&Out[(size_t)(row + 8) * QKdim + col]  = v1;
        }
    }
}

// ---------------------------------------------------------------------------
// K2: sumexp[b,n] = sum_m exp(scale * Q[b,n,:]·K[b,m,:])
//   grid (32 n-tiles, 8 b), 256 threads, Q tile resident, stream 32 K tiles.
// ---------------------------------------------------------------------------
#define SLD 136      // smem row stride (bf16) for 128-wide k, conflict-free
#define SCALE 0.08838834764831845f   // 128^-0.5

extern __shared__ char s_dyn[];

__global__ __launch_bounds__(256, 2) void sumexp_kernel() {
    __nv_bfloat16* Qs = (__nv_bfloat16*)s_dyn;
    __nv_bfloat16* Ks = Qs + 128 * SLD;
    float* red = (float*)(Ks + 128 * SLD);

    const int n0 = blockIdx.x * 128;
    const int b = blockIdx.y;
    const int tid = threadIdx.x;
    const int wid = tid >> 5, lane = tid & 31;
    const int warp_m = wid >> 2, warp_n = wid & 3;
    const int q = lane >> 2, r = lane & 3;

    // load Q tile (128 x 128 bf16) once
    {
        uint4 qv[8];
#pragma unroll
        for (int i = 0; i < 8; i++) {
            int lin = tid + i * 256;
            int row = lin >> 4, cc = lin & 15;
            qv[i] = *(const uint4*)&g_Qb[((size_t)(b * Ndim + n0 + row)) * QKdim + cc * 8];
        }
#pragma unroll
        for (int i = 0; i < 8; i++) {
            int lin = tid + i * 256;
            int row = lin >> 4, cc = lin & 15;
            *(uint4*)&Qs[row * SLD + cc * 8] = qv[i];
        }
    }

    float rs[8];
#pragma unroll
    for (int i = 0; i < 8; i++) rs[i] = 0.f;

    for (int mc = 0; mc < 32; mc++) {
        const int m0 = mc * 128;
        uint4 kv[8];
#pragma unroll
        for (int i = 0; i < 8; i++) {
            int lin = tid + i * 256;
            int row = lin >> 4, cc = lin & 15;
            kv[i] = *(const uint4*)&g_Kb[((size_t)(b * Ndim + m0 + row)) * QKdim + cc * 8];
        }
        __syncthreads();   // previous chunk fully consumed (also covers Q stores)
#pragma unroll
        for (int i = 0; i < 8; i++) {
            int lin = tid + i * 256;
            int row = lin >> 4, cc = lin & 15;
            *(uint4*)&Ks[row * SLD + cc * 8] = kv[i];
        }
        __syncthreads();

        float c[4][4][4];
#pragma unroll
        for (int mi = 0; mi < 4; mi++)
#pragma unroll
            for (int ni = 0; ni < 4; ni++)
#pragma unroll
                for (int j = 0; j < 4; j++) c[mi][ni][j] = 0.f;

#pragma unroll
        for (int kk = 0; kk < 8; kk++) {
            const int kof = kk * 16;
            uint32_t af[4][4], bfg[4][2];
#pragma unroll
            for (int mi = 0; mi < 4; mi++) {
                const __nv_bfloat16* p = &Qs[(warp_m * 64 + mi * 16 + q) * SLD + kof + 2 * r];
                af[mi][0] = *(const uint32_t*)p;
                af[mi][1] = *(const uint32_t*)(p + 8 * SLD);
                af[mi][2] = *(const uint32_t*)(p + 8);
                af[mi][3] = *(const uint32_t*)(p + 8 * SLD + 8);
            }
#pragma unroll
            for (int ni = 0; ni < 4; ni++) {
                const __nv_bfloat16* p = &Ks[(warp_n * 32 + ni * 8 + q) * SLD + kof + 2 * r];
                bfg[ni][0] = *(const uint32_t*)p;
                bfg[ni][1] = *(const uint32_t*)(p + 8);
            }
#pragma unroll
            for (int mi = 0; mi < 4; mi++)
#pragma unroll
                for (int ni = 0; ni < 4; ni++)
                    mma16816(c[mi][ni], af[mi], bfg[ni]);
        }

        // exp + row accumulate
#pragma unroll
        for (int mi = 0; mi < 4; mi++)
#pragma unroll
            for (int ni = 0; ni < 4; ni++) {
                rs[mi * 2]     += __expf(c[mi][ni][0] * SCALE) + __expf(c[mi][ni][1] * SCALE);
                rs[mi * 2 + 1] += __expf(c[mi][ni][2] * SCALE) + __expf(c[mi][ni][3] * SCALE);
            }
    }

    // reduce rs across the 4 lanes sharing each row (lane%4)
#pragma unroll
    for (int i = 0; i < 8; i++) {
        rs[i] += __shfl_xor_sync(0xffffffffu, rs[i], 1);
        rs[i] += __shfl_xor_sync(0xffffffffu, rs[i], 2);
    }

    __syncthreads();
    if (tid < 128) red[tid] = 0.f;
    __syncthreads();
    if (r == 0) {
#pragma unroll
        for (int mi = 0; mi < 4; mi++) {
            atomicAdd(&red[warp_m * 64 + mi * 16 + q],     rs[mi * 2]);
            atomicAdd(&red[warp_m * 64 + mi * 16 + q + 8], rs[mi * 2 + 1]);
        }
    }
    __syncthreads();
    if (tid < 128) g_sumexp[b * Ndim + n0 + tid] = red[tid];
}

// ---------------------------------------------------------------------------
// K3: w_keep = sumexp / sum_n(sumexp)      ( == softmax(logsumexp) )
// ---------------------------------------------------------------------------
__global__ void wkeep_kernel() {
    int b = blockIdx.x;
    int tid = threadIdx.x;
    __shared__ float sm[256];
    float s = 0.f;
    for (int n = tid; n < Ndim; n += 256) s += g_sumexp[b * Ndim + n];
    sm[tid] = s; __syncthreads();
    for (int st = 128; st > 0; st >>= 1) { if (tid < st) sm[tid] += sm[tid + st]; __syncthreads(); }
    float inv = 1.0f / sm[0];
    for (int n = tid; n < Ndim; n += 256)
        g_wkeep[b * Ndim + n] = g_sumexp[b * Ndim + n] * inv;
}

// ---------------------------------------------------------------------------
// K4: norm[b,m] = sum_n slot_w[m,n]*w_keep[b,n].   grid 256 = b*32+m
// ---------------------------------------------------------------------------
__global__ void norm_kernel() {
    int bm = blockIdx.x;
    int b = bm >> 5, m = bm & 31;
    int tid = threadIdx.x;
    __shared__ float sm[256];
    float s = 0.f;
    for (int n = tid; n < Ndim; n += 256)
        s += g_slotw[m * Ndim + n] * g_wkeep[b * Ndim + n];
    sm[tid] = s; __syncthreads();
    for (int st = 128; st > 0; st >>= 1) { if (tid < st) sm[tid] += sm[tid + st]; __syncthreads(); }
    if (tid == 0) g_norm[bm] = s = sm[0];
}

// ---------------------------------------------------------------------------
// K5: partial out accumulation (deterministic, no atomics).
//   grid (32 n-chunks, 8 b), 256 threads. thread t handles d = t, all 32 m.
// ---------------------------------------------------------------------------
__global__ __launch_bounds__(256) void out_accum_kernel(const float* __restrict__ H0) {
    const int nc = blockIdx.x, b = blockIdx.y;
    const int n0 = nc * 128;
    const int tid = threadIdx.x;
    __shared__ float coefT[128 * 32];   // [n][m]

#pragma unroll
    for (int i = 0; i < 16; i++) {
        int lin = tid + i * 256;
        int n = lin >> 5, m = lin & 31;
        coefT[n * 32 + m] = g_slotw[m * Ndim + n0 + n] * g_wkeep[b * Ndim + n0 + n];
    }
    __syncthreads();

    float acc[32];
#pragma unroll
    for (int m = 0; m < 32; m++) acc[m] = 0.f;

    const float* H = H0 + ((size_t)b * Ndim + n0) * Ddim + tid;
#pragma unroll 4
    for (int n = 0; n < 128; n++) {
        float h = H[(size_t)n * Ddim];
        const float4* cp = (const float4*)&coefT[n * 32];
#pragma unroll
        for (int j = 0; j < 8; j++) {
            float4 c4 = cp[j];
            acc[j * 4 + 0] = fmaf(c4.x, h, acc[j * 4 + 0]);
            acc[j * 4 + 1] = fmaf(c4.y, h, acc[j * 4 + 1]);
            acc[j * 4 + 2] = fmaf(c4.z, h, acc[j * 4 + 2]);
            acc[j * 4 + 3] = fmaf(c4.w, h, acc[j * 4 + 3]);
        }
    }

    float* dst = &g_part[(((size_t)b * 32 + nc) * Mdim) * Ddim + tid];
#pragma unroll
    for (int m = 0; m < 32; m++) dst[(size_t)m * Ddim] = acc[m];
}

// ---------------------------------------------------------------------------
// K6: reduce partials over 32 n-chunks + normalize -> final out
// ---------------------------------------------------------------------------
__global__ void reduce_out_kernel(float* __restrict__ out) {
    int idx = blockIdx.x * 256 + threadIdx.x;   // 65536
    int d = idx & 255;
    int m = (idx >> 8) & 31;
    int b = idx >> 13;
    float s = 0.f;
#pragma unroll
    for (int nc = 0; nc < 32; nc++)
        s += g_part[(((size_t)b * 32 + nc) * Mdim + m) * Ddim + d];
    out[idx] = s / (g_norm[b * 32 + m] + 1e-6f);
}

// ---------------------------------------------------------------------------
// launch
// ---------------------------------------------------------------------------
extern "C" void kernel_launch(void* const* d_in, const int* in_sizes, int n_in,
                              void* d_out, int out_size) {
    const float* X0   = (const float*)d_in[0];
    const float* H0   = (const float*)d_in[1];
    const float* Wq   = (const float*)d_in[2];
    const float* Wk   = (const float*)d_in[3];
    const float* slot = (const float*)d_in[4];
    float* out = (float*)d_out;

    const int SMEM_S = (128 * SLD * 2) * 2 + 128 * 4;   // Qs + Ks + red = 70144
    cudaFuncSetAttribute(sumexp_kernel, cudaFuncAttributeMaxDynamicSharedMemorySize, SMEM_S);

    prep_wt_kernel<<<128, 256>>>(Wq, Wk);
    slot_softmax_kernel<<<32, 256>>>(slot);
    proj_kernel<<<dim3(256, 2), 256>>>(H0, X0);
    sumexp_kernel<<<dim3(32, 8), 256, SMEM_S>>>();
    wkeep_kernel<<<8, 256>>>();
    norm_kernel<<<256, 256>>>();
    out_accum_kernel<<<dim3(32, 8), 256>>>(H0);
    reduce_out_kernel<<<256, 256>>>(out);
    (void)in_sizes; (void)n_in; (void)out_size;
}

// round 3
// speedup vs baseline: 1.0728x; 1.0728x over previous
#include <cuda_runtime.h>
#include <cuda_bf16.h>
#include <cstdint>

// ============================================================================
// Problem: B=8, N=4096, D=256, QK=128, M=32
//   Q = H0 @ Wq ; K = X0 @ Wk
//   sumexp[b,n] = sum_m exp(scale * Q[b,n,:]·K[b,m,:])
//   w_keep = sumexp / sum(sumexp)  ( == softmax(logsumexp(S)) )
//   slot_w = softmax(slot_logits); w = slot_w * w_keep; w /= (sum + 1e-6)
//   out = w @ H0
// R3: mma.sync path (tcgen05 unavailable: harness compiles .target sm_100).
//     sumexp: cp.async double-buffer + ldmatrix fragment loads.
// ============================================================================

#define Bdim 8
#define Ndim 4096
#define Ddim 256
#define QKdim 128
#define Mdim 32

// -------- device scratch --------
__device__ __nv_bfloat16 g_Qb[Bdim * Ndim * QKdim];     // 8 MB
__device__ __nv_bfloat16 g_Kb[Bdim * Ndim * QKdim];     // 8 MB
__device__ __nv_bfloat16 g_Wt[2][QKdim * Ddim];
__device__ float g_sumexp[Bdim * Ndim];
__device__ float g_wkeep[Bdim * Ndim];
__device__ float g_slotw[Mdim * Ndim];
__device__ float g_norm[Bdim * Mdim];
__device__ float g_part[Bdim * 32 * Mdim * Ddim];       // 8 MB partials

// ---------------------------------------------------------------------------
// helpers
// ---------------------------------------------------------------------------
__device__ __forceinline__ uint32_t smem_u32(const void* p) {
    uint32_t a;
    asm("{ .reg .u64 t; cvta.to.shared.u64 t, %1; cvt.u32.u64 %0, t; }" : "=r"(a) : "l"(p));
    return a;
}
__device__ __forceinline__ float ex2f(float x) {
    float r; asm("ex2.approx.ftz.f32 %0, %1;" : "=f"(r) : "f"(x)); return r;
}
#define CP_ASYNC16(dst, src) \
    asm volatile("cp.async.cg.shared.global [%0], [%1], 16;" :: "r"(dst), "l"(src))
#define CP_COMMIT() asm volatile("cp.async.commit_group;" ::: "memory")
#define CP_WAIT1()  asm volatile("cp.async.wait_group 1;" ::: "memory")
#define CP_WAIT0()  asm volatile("cp.async.wait_group 0;" ::: "memory")

__device__ __forceinline__ void mma16816(float* c, const uint32_t* a, const uint32_t* b) {
    asm volatile(
        "mma.sync.aligned.m16n8k16.row.col.f32.bf16.bf16.f32 "
        "{%0,%1,%2,%3}, {%4,%5,%6,%7}, {%8,%9}, {%0,%1,%2,%3};"
        : "+f"(c[0]), "+f"(c[1]), "+f"(c[2]), "+f"(c[3])
        : "r"(a[0]), "r"(a[1]), "r"(a[2]), "r"(a[3]), "r"(b[0]), "r"(b[1]));
}
__device__ __forceinline__ void ldsm_x4(uint32_t* r, uint32_t addr) {
    asm volatile("ldmatrix.sync.aligned.m8n8.x4.shared.b16 {%0,%1,%2,%3}, [%4];"
                 : "=r"(r[0]), "=r"(r[1]), "=r"(r[2]), "=r"(r[3]) : "r"(addr));
}

// ---------------------------------------------------------------------------
// K0: transpose + convert Wq, Wk to bf16
// ---------------------------------------------------------------------------
__global__ void prep_wt_kernel(const float* __restrict__ Wq, const float* __restrict__ Wk) {
    int idx = blockIdx.x * blockDim.x + threadIdx.x;
    if (idx < Ddim * QKdim) {
        int q = idx >> 8;
        int d = idx & 255;
        g_Wt[0][q * Ddim + d] = __float2bfloat16(Wq[d * QKdim + q]);
        g_Wt[1][q * Ddim + d] = __float2bfloat16(Wk[d * QKdim + q]);
    }
}

// ---------------------------------------------------------------------------
// K0b: slot_w = softmax(slot_logits, axis=-1)
// ---------------------------------------------------------------------------
__global__ void slot_softmax_kernel(const float* __restrict__ logits) {
    int m = blockIdx.x;
    int tid = threadIdx.x;
    __shared__ float sred[256];
    const float* row = logits + m * Ndim;

    float mx = -1e30f;
    for (int n = tid; n < Ndim; n += 256) mx = fmaxf(mx, row[n]);
    sred[tid] = mx; __syncthreads();
    for (int s = 128; s > 0; s >>= 1) { if (tid < s) sred[tid] = fmaxf(sred[tid], sred[tid + s]); __syncthreads(); }
    mx = sred[0]; __syncthreads();

    float sum = 0.f;
    for (int n = tid; n < Ndim; n += 256) sum += __expf(row[n] - mx);
    sred[tid] = sum; __syncthreads();
    for (int s = 128; s > 0; s >>= 1) { if (tid < s) sred[tid] += sred[tid + s]; __syncthreads(); }
    float inv = 1.0f / sred[0];

    for (int n = tid; n < Ndim; n += 256)
        g_slotw[m * Ndim + n] = __expf(row[n] - mx) * inv;
}

// ---------------------------------------------------------------------------
// K1: projection GEMM with register prefetch of next k-chunk.
// ---------------------------------------------------------------------------
#define PLDA 40

__global__ __launch_bounds__(256) void proj_kernel(const float* __restrict__ H0,
                                                   const float* __restrict__ X0) {
    const int z = blockIdx.y;
    const float* A = z ? X0 : H0;
    const __nv_bfloat16* W = g_Wt[z];
    __nv_bfloat16* Out = z ? g_Kb : g_Qb;
    const int row0 = blockIdx.x * 128;

    __shared__ __nv_bfloat16 As[128 * PLDA];
    __shared__ __nv_bfloat16 Bs[128 * PLDA];

    const int tid = threadIdx.x;
    const int wid = tid >> 5, lane = tid & 31;
    const int warp_m = wid >> 2, warp_n = wid & 3;
    const int q = lane >> 2, r = lane & 3;

    float c[4][4][4];
#pragma unroll
    for (int mi = 0; mi < 4; mi++)
#pragma unroll
        for (int ni = 0; ni < 4; ni++)
#pragma unroll
            for (int j = 0; j < 4; j++) c[mi][ni][j] = 0.f;

    const int arow = tid >> 3, ac4 = tid & 7;      // A: 128 rows x 8 float4
    const int brow0 = tid >> 4, bcc = tid & 15;    // B: 128 rows x 16 u32

    float4 av[4];
    uint32_t bv[8];
#pragma unroll
    for (int i = 0; i < 4; i++)
        av[i] = *(const float4*)&A[(size_t)(row0 + arow + i * 32) * Ddim + ac4 * 4];
#pragma unroll
    for (int i = 0; i < 8; i++)
        bv[i] = *(const uint32_t*)&W[(brow0 + i * 16) * Ddim + bcc * 2];

    for (int k0 = 0; k0 < Ddim; k0 += 32) {
        __syncthreads();
#pragma unroll
        for (int i = 0; i < 4; i++) {
            __nv_bfloat162 p0, p1;
            p0.x = __float2bfloat16(av[i].x); p0.y = __float2bfloat16(av[i].y);
            p1.x = __float2bfloat16(av[i].z); p1.y = __float2bfloat16(av[i].w);
            *(__nv_bfloat162*)&As[(arow + i * 32) * PLDA + ac4 * 4]     = p0;
            *(__nv_bfloat162*)&As[(arow + i * 32) * PLDA + ac4 * 4 + 2] = p1;
        }
#pragma unroll
        for (int i = 0; i < 8; i++)
            *(uint32_t*)&Bs[(brow0 + i * 16) * PLDA + bcc * 2] = bv[i];
        __syncthreads();

        // prefetch next chunk while computing this one
        if (k0 + 32 < Ddim) {
#pragma unroll
            for (int i = 0; i < 4; i++)
                av[i] = *(const float4*)&A[(size_t)(row0 + arow + i * 32) * Ddim + k0 + 32 + ac4 * 4];
#pragma unroll
            for (int i = 0; i < 8; i++)
                bv[i] = *(const uint32_t*)&W[(brow0 + i * 16) * Ddim + k0 + 32 + bcc * 2];
        }

#pragma unroll
        for (int ks = 0; ks < 32; ks += 16) {
            uint32_t af[4][4], bfg[4][2];
#pragma unroll
            for (int mi = 0; mi < 4; mi++) {
                const __nv_bfloat16* p = &As[(warp_m * 64 + mi * 16 + q) * PLDA + ks + 2 * r];
                af[mi][0] = *(const uint32_t*)p;
                af[mi][1] = *(const uint32_t*)(p + 8 * PLDA);
                af[mi][2] = *(const uint32_t*)(p + 8);
                af[mi][3] = *(const uint32_t*)(p + 8 * PLDA + 8);
            }
#pragma unroll
            for (int ni = 0; ni < 4; ni++) {
                const __nv_bfloat16* p = &Bs[(warp_n * 32 + ni * 8 + q) * PLDA + ks + 2 * r];
                bfg[ni][0] = *(const uint32_t*)p;
                bfg[ni][1] = *(const uint32_t*)(p + 8);
            }
#pragma unroll
            for (int mi = 0; mi < 4; mi++)
#pragma unroll
                for (int ni = 0; ni < 4; ni++)
                    mma16816(c[mi][ni], af[mi], bfg[ni]);
        }
    }

#pragma unroll
    for (int mi = 0; mi < 4; mi++) {
        int row = row0 + warp_m * 64 + mi * 16 + q;
#pragma unroll
        for (int ni = 0; ni < 4; ni++) {
            int col = warp_n * 32 + ni * 8 + 2 * r;
            __nv_bfloat162 v0, v1;
            v0.x = __float2bfloat16(c[mi][ni][0]); v0.y = __float2bfloat16(c[mi][ni][1]);
            v1.x = __float2bfloat16(c[mi][ni][2]); v1.y = __float2bfloat16(c[mi][ni][3]);
            *(__nv_bfloat162*)&Out[(size_t)row * QKdim + col]        = v0;
            *(__nv_bfloat162*)&Out[(size_t)(row + 8) * QKdim + col]  = v1;
        }
    }
}

// ---------------------------------------------------------------------------
// K2: sumexp[b,n] = sum_m exp(scale * Q[b,n,:]·K[b,m,:])
//   grid (32 n-tiles, 8 b), 256 threads. Q tile resident in smem; K chunks
//   (128 rows) double-buffered via cp.async; fragments via ldmatrix.x4.
// ---------------------------------------------------------------------------
#define CEX   (0.08838834764831845f * 1.4426950408889634f)   // 128^-0.5 * log2(e)
#define KLDB  272                   // smem row stride in BYTES (136 bf16)
#define TILEB (128 * KLDB)          // 34816 bytes per 128x128 tile

extern __shared__ char s_dyn[];

// stage a 128x128 bf16 row-major gmem tile into padded smem via cp.async
__device__ __forceinline__ void stage128(uint32_t sdst, const __nv_bfloat16* g, int tid) {
#pragma unroll
    for (int i = 0; i < 8; i++) {
        int lin = tid + i * 256;
        int row = lin >> 4, cc = lin & 15;
        CP_ASYNC16(sdst + row * KLDB + cc * 16, g + row * 128 + cc * 8);
    }
}

__global__ __launch_bounds__(256, 2) void sumexp_kernel() {
    const uint32_t sb = smem_u32(s_dyn);
    const uint32_t sQ = sb, sK0 = sb + TILEB, sK1 = sb + 2 * TILEB;
    __shared__ float red[128];

    const int n0 = blockIdx.x * 128;
    const int b = blockIdx.y;
    const int tid = threadIdx.x;
    const int wid = tid >> 5, lane = tid & 31;
    const int warp_m = wid >> 2, warp_n = wid & 3;
    const int q = lane >> 2, r = lane & 3;

    const __nv_bfloat16* Qg = g_Qb + ((size_t)(b * Ndim) + n0) * QKdim;
    const __nv_bfloat16* Kg = g_Kb + (size_t)(b * Ndim) * QKdim;

    // prologue: Q + chunk0 (group0), chunk1 (group1)
    stage128(sQ, Qg, tid);
    stage128(sK0, Kg, tid);
    CP_COMMIT();
    stage128(sK1, Kg + 128 * 128, tid);
    CP_COMMIT();
    CP_WAIT1();            // Q + chunk0 ready
    __syncthreads();

    // ldmatrix address bases
    // A (x4): lanes 0-7 rows r0..r0+7 col0 | 8-15 rows+8 col0 | 16-23 rows col+16B | 24-31 rows+8 col+16B
    const int arow = warp_m * 64 + ((lane >> 3) & 1) * 8 + (lane & 7);
    const uint32_t acol = (lane >> 4) * 16;
    uint32_t aaddr[4];
#pragma unroll
    for (int mi = 0; mi < 4; mi++) aaddr[mi] = sQ + (arow + mi * 16) * KLDB + acol;
    // B (x4): lanes 0-7 n0..n0+7 k0 | 8-15 n0..7 k+16B | 16-23 n+8 k0 | 24-31 n+8 k+16B
    const int brow = warp_n * 32 + ((lane >> 4) & 1) * 8 + (lane & 7);
    const uint32_t bcol = ((lane >> 3) & 1) * 16;
    const uint32_t boff = brow * KLDB + bcol;

    float acc0 = 0.f, acc1 = 0.f, acc2 = 0.f, acc3 = 0.f;
    float rs[8];

    for (int mc = 0; mc < 32; mc++) {
        const uint32_t kbase = ((mc & 1) ? sK1 : sK0) + boff;

        float c[4][4][4];
#pragma unroll
        for (int mi = 0; mi < 4; mi++)
#pragma unroll
            for (int ni = 0; ni < 4; ni++)
#pragma unroll
                for (int j = 0; j < 4; j++) c[mi][ni][j] = 0.f;

#pragma unroll
        for (int kk = 0; kk < 8; kk++) {
            const uint32_t ko = kk * 32;
            uint32_t af[4][4], bq[2][4];
#pragma unroll
            for (int mi = 0; mi < 4; mi++) ldsm_x4(af[mi], aaddr[mi] + ko);
#pragma unroll
            for (int np = 0; np < 2; np++) ldsm_x4(bq[np], kbase + np * 16 * KLDB + ko);
#pragma unroll
            for (int mi = 0; mi < 4; mi++)
#pragma unroll
                for (int ni = 0; ni < 4; ni++)
                    mma16816(c[mi][ni], af[mi], &bq[ni >> 1][(ni & 1) * 2]);
        }

        // exp + row accumulate
#pragma unroll
        for (int mi = 0; mi < 4; mi++) {
            float s0 = 0.f, s1 = 0.f;
#pragma unroll
            for (int ni = 0; ni < 4; ni++) {
                s0 += ex2f(c[mi][ni][0] * CEX) + ex2f(c[mi][ni][1] * CEX);
                s1 += ex2f(c[mi][ni][2] * CEX) + ex2f(c[mi][ni][3] * CEX);
            }
            if (mi == 0) { acc0 += s0; acc1 += s1; }
            else if (mi == 1) { acc2 += s0; acc3 += s1; }
            else {
                rs[mi * 2] += s0; rs[mi * 2 + 1] += s1;   // mi=2,3 use rs[4..7]
            }
        }
        if (mc == 0) { rs[0] = rs[1] = rs[2] = rs[3] = 0.f; }  // keep rs[4..7] live only

        __syncthreads();                       // everyone done reading buf mc&1
        if (mc + 2 < 32)
            stage128((mc & 1) ? sK1 : sK0, Kg + (size_t)(mc + 2) * 128 * 128, tid);
        CP_COMMIT();
        CP_WAIT1();                            // chunk mc+1 complete
        __syncthreads();
    }
    rs[0] = acc0; rs[1] = acc1; rs[2] = acc2; rs[3] = acc3;

    // reduce across lanes sharing each row (lane & 3)
#pragma unroll
    for (int i = 0; i < 8; i++) {
        rs[i] += __shfl_xor_sync(0xffffffffu, rs[i], 1);
        rs[i] += __shfl_xor_sync(0xffffffffu, rs[i], 2);
    }
    if (tid < 128) red[tid] = 0.f;
    __syncthreads();
    if (r == 0) {
#pragma unroll
        for (int mi = 0; mi < 4; mi++) {
            atomicAdd(&red[warp_m * 64 + mi * 16 + q],     rs[mi * 2]);
            atomicAdd(&red[warp_m * 64 + mi * 16 + q + 8], rs[mi * 2 + 1]);
        }
    }
    __syncthreads();
    if (tid < 128) g_sumexp[b * Ndim + n0 + tid] = red[tid];
}

// fix-up note: rs[0..3] for mi=0,1 are kept in acc0..acc3 to help the
// register allocator; they are merged back just before the shuffle reduce.

// ---------------------------------------------------------------------------
// K3: w_keep = sumexp / sum_n(sumexp)
// ---------------------------------------------------------------------------
__global__ void wkeep_kernel() {
    int b = blockIdx.x;
    int tid = threadIdx.x;
    __shared__ float sm[256];
    float s = 0.f;
    for (int n = tid; n < Ndim; n += 256) s += g_sumexp[b * Ndim + n];
    sm[tid] = s; __syncthreads();
    for (int st = 128; st > 0; st >>= 1) { if (tid < st) sm[tid] += sm[tid + st]; __syncthreads(); }
    float inv = 1.0f / sm[0];
    for (int n = tid; n < Ndim; n += 256)
        g_wkeep[b * Ndim + n] = g_sumexp[b * Ndim + n] * inv;
}

// ---------------------------------------------------------------------------
// K4: norm[b,m] = sum_n slot_w[m,n]*w_keep[b,n]
// ---------------------------------------------------------------------------
__global__ void norm_kernel() {
    int bm = blockIdx.x;
    int b = bm >> 5, m = bm & 31;
    int tid = threadIdx.x;
    __shared__ float sm[256];
    float s = 0.f;
    for (int n = tid; n < Ndim; n += 256)
        s += g_slotw[m * Ndim + n] * g_wkeep[b * Ndim + n];
    sm[tid] = s; __syncthreads();
    for (int st = 128; st > 0; st >>= 1) { if (tid < st) sm[tid] += sm[tid + st]; __syncthreads(); }
    if (tid == 0) g_norm[bm] = sm[0];
}

// ---------------------------------------------------------------------------
// K5: partial out accumulation (deterministic)
// ---------------------------------------------------------------------------
__global__ __launch_bounds__(256) void out_accum_kernel(const float* __restrict__ H0) {
    const int nc = blockIdx.x, b = blockIdx.y;
    const int n0 = nc * 128;
    const int tid = threadIdx.x;
    __shared__ float coefT[128 * 32];

#pragma unroll
    for (int i = 0; i < 16; i++) {
        int lin = tid + i * 256;
        int n = lin >> 5, m = lin & 31;
        coefT[n * 32 + m] = g_slotw[m * Ndim + n0 + n] * g_wkeep[b * Ndim + n0 + n];
    }
    __syncthreads();

    float acc[32];
#pragma unroll
    for (int m = 0; m < 32; m++) acc[m] = 0.f;

    const float* H = H0 + ((size_t)b * Ndim + n0) * Ddim + tid;
#pragma unroll 4
    for (int n = 0; n < 128; n++) {
        float h = H[(size_t)n * Ddim];
        const float4* cp = (const float4*)&coefT[n * 32];
#pragma unroll
        for (int j = 0; j < 8; j++) {
            float4 c4 = cp[j];
            acc[j * 4 + 0] = fmaf(c4.x, h, acc[j * 4 + 0]);
            acc[j * 4 + 1] = fmaf(c4.y, h, acc[j * 4 + 1]);
            acc[j * 4 + 2] = fmaf(c4.z, h, acc[j * 4 + 2]);
            acc[j * 4 + 3] = fmaf(c4.w, h, acc[j * 4 + 3]);
        }
    }

    float* dst = &g_part[(((size_t)b * 32 + nc) * Mdim) * Ddim + tid];
#pragma unroll
    for (int m = 0; m < 32; m++) dst[(size_t)m * Ddim] = acc[m];
}

// ---------------------------------------------------------------------------
// K6: reduce partials + normalize
// ---------------------------------------------------------------------------
__global__ void reduce_out_kernel(float* __restrict__ out) {
    int idx = blockIdx.x * 256 + threadIdx.x;
    int d = idx & 255;
    int m = (idx >> 8) & 31;
    int b = idx >> 13;
    float s = 0.f;
#pragma unroll
    for (int nc = 0; nc < 32; nc++)
        s += g_part[(((size_t)b * 32 + nc) * Mdim + m) * Ddim + d];
    out[idx] = s / (g_norm[b * 32 + m] + 1e-6f);
}

// ---------------------------------------------------------------------------
// launch
// ---------------------------------------------------------------------------
extern "C" void kernel_launch(void* const* d_in, const int* in_sizes, int n_in,
                              void* d_out, int out_size) {
    const float* X0   = (const float*)d_in[0];
    const float* H0   = (const float*)d_in[1];
    const float* Wq   = (const float*)d_in[2];
    const float* Wk   = (const float*)d_in[3];
    const float* slot = (const float*)d_in[4];
    float* out = (float*)d_out;

    const int SMEM_S = 3 * TILEB;   // 104448
    cudaFuncSetAttribute(sumexp_kernel, cudaFuncAttributeMaxDynamicSharedMemorySize, SMEM_S);

    prep_wt_kernel<<<128, 256>>>(Wq, Wk);
    slot_softmax_kernel<<<32, 256>>>(slot);
    proj_kernel<<<dim3(256, 2), 256>>>(H0, X0);
    sumexp_kernel<<<dim3(32, 8), 256, SMEM_S>>>();
    wkeep_kernel<<<8, 256>>>();
    norm_kernel<<<256, 256>>>();
    out_accum_kernel<<<dim3(32, 8), 256>>>(H0);
    reduce_out_kernel<<<256, 256>>>(out);
    (void)in_sizes; (void)n_in; (void)out_size;
}